// round 7
// baseline (speedup 1.0000x reference)
#include <cuda_runtime.h>
#include <math.h>

#define TT  100
#define HH  50
#define ZZ  10
#define OUTD 65          // ZZ + ZZ*(ZZ+1)/2
#define NTRI 55          // ZZ*(ZZ+1)/2
#define LN_EPS 1e-6f
#define NTHREADS 96

// scratch for hs (T x H) + progress flag — __device__ globals, no allocation
__device__ float g_hs[TT * HH];
__device__ int   g_prog;          // monotone step counter (chunked)

// ---------------- packed f32x2 helpers (Blackwell) ----------------
__device__ __forceinline__ unsigned long long pk2(float lo, float hi) {
    unsigned long long r;
    asm("mov.b64 %0, {%1, %2};" : "=l"(r) : "f"(lo), "f"(hi));
    return r;
}
__device__ __forceinline__ void upk2(unsigned long long v, float& lo, float& hi) {
    asm("mov.b64 {%0, %1}, %2;" : "=f"(lo), "=f"(hi) : "l"(v));
}
__device__ __forceinline__ unsigned long long fma2(
    unsigned long long a, unsigned long long b, unsigned long long c) {
    unsigned long long d;
    asm("fma.rn.f32x2 %0, %1, %2, %3;" : "=l"(d) : "l"(a), "l"(b), "l"(c));
    return d;
}
__device__ __forceinline__ unsigned long long add2(
    unsigned long long a, unsigned long long b) {
    unsigned long long d;
    asm("add.rn.f32x2 %0, %1, %2;" : "=l"(d) : "l"(a), "l"(b));
    return d;
}

__device__ __forceinline__ float fast_sigmoid(float x) {
    float e = __expf(-x);
    return __fdividef(1.0f, 1.0f + e);
}
__device__ __forceinline__ float fast_tanh(float x) {
    float e = __expf(-2.0f * fabsf(x));
    float t = __fdividef(1.0f - e, 1.0f + e);
    return copysignf(t, x);
}

// ---------------------------------------------------------------------------
// Recurrence (CTA 0): R6 design with FFMA2 matvec.
// 3 warps, warp g owns gate g. Lane l owns columns 2l, 2l+1 (active l < 25).
// Weights packed along i as u64 f32x2 pairs; h in registers, broadcast by
// 2 SHFLs per i-pair straight into the packed operand. ONE __syncthreads per
// step; parity-double-buffered gate exchange; g_hs stores split across warps.
// ---------------------------------------------------------------------------
__device__ __forceinline__ void recurrence_body(
    const float* __restrict__ carry_init,
    const float* __restrict__ W_hr, const float* __restrict__ b_hr,
    const float* __restrict__ s_r,  const float* __restrict__ o_r,
    const float* __restrict__ W_hz, const float* __restrict__ b_hz,
    const float* __restrict__ s_z,  const float* __restrict__ o_z,
    const float* __restrict__ W_hn, const float* __restrict__ b_hn,
    const float* __restrict__ s_n,  const float* __restrict__ o_n)
{
    __shared__ float gate_sh[2][3][64];   // [parity][gate][col] (padded rows)

    const int tid  = threadIdx.x;
    const int g    = tid >> 5;            // warp = gate, 0..2
    const int l    = tid & 31;            // lane
    const bool act = (l < 25);
    const int c0   = act ? 2 * l : 0;     // clamped for inactive lanes
    // g_hs store ownership: warp0 -> pairs 0-8, warp1 -> 9-16, warp2 -> 17-24
    const int owner = (l < 9) ? 0 : (l < 17) ? 1 : 2;

    const float* Wg = (g == 0) ? W_hr : (g == 1) ? W_hz : W_hn;
    const float* bg = (g == 0) ? b_hr : (g == 1) ? b_hz : b_hn;
    const float* sg = (g == 0) ? s_r  : (g == 1) ? s_z  : s_n;
    const float* og = (g == 0) ? o_r  : (g == 1) ? o_z  : o_n;

    // Weights packed along i: wx[p] = (W[2p][c0], W[2p+1][c0]); wy for c0+1.
    unsigned long long wx[25], wy[25];
    #pragma unroll
    for (int p = 0; p < 25; p++) {
        const float* r0 = Wg + (2 * p)     * HH + c0;
        const float* r1 = Wg + (2 * p + 1) * HH + c0;
        wx[p] = pk2(r0[0], r1[0]);
        wy[p] = pk2(r0[1], r1[1]);
    }
    const float b0 = bg[c0], b1 = bg[c0 + 1];
    const float sc0 = sg[c0], sc1 = sg[c0 + 1];
    const float of0 = og[c0], of1 = og[c0 + 1];

    // h state in registers (lane l holds h[2l], h[2l+1])
    float h0 = carry_init[c0];
    float h1 = carry_init[c0 + 1];

    for (int t = 0; t < TT; t++) {
        // ---- matvec: 50 SHFL + 50 FFMA2 (fma-pipe cost halved vs scalar)
        unsigned long long axe = 0ull, axo = 0ull, aye = 0ull, ayo = 0ull;
        #pragma unroll
        for (int p = 0; p < 25; p++) {
            float lo = __shfl_sync(0xffffffffu, h0, p);
            float hi = __shfl_sync(0xffffffffu, h1, p);
            unsigned long long hp = pk2(lo, hi);   // (h[2p], h[2p+1])
            if (p & 1) { axo = fma2(hp, wx[p], axo); ayo = fma2(hp, wy[p], ayo); }
            else       { axe = fma2(hp, wx[p], axe); aye = fma2(hp, wy[p], aye); }
        }
        float e0, e1, f0, f1;
        upk2(add2(axe, axo), e0, e1);
        upk2(add2(aye, ayo), f0, f1);
        float px = e0 + e1 + b0;
        float py = f0 + f1 + b1;

        // ---- in-warp layernorm stats: 5-step butterfly, 2 indep SHFL/step
        float sv = 0.f, qv = 0.f;
        if (act) { sv = px + py; qv = px * px + py * py; }
        #pragma unroll
        for (int off = 16; off; off >>= 1) {
            sv += __shfl_xor_sync(0xffffffffu, sv, off);
            qv += __shfl_xor_sync(0xffffffffu, qv, off);
        }
        float mean = sv * (1.0f / HH);
        float var  = qv * (1.0f / HH) - mean * mean;
        float inv  = rsqrtf(var + LN_EPS);

        float nx = (px - mean) * inv * sc0 + of0;
        float ny = (py - mean) * inv * sc1 + of1;

        float gx, gy;
        if (g < 2) { gx = fast_sigmoid(nx); gy = fast_sigmoid(ny); }
        else       { gx = nx;               gy = ny;               }

        const int buf = t & 1;
        if (act)
            *reinterpret_cast<float2*>(&gate_sh[buf][g][c0]) = make_float2(gx, gy);
        __syncthreads();                       // the ONE barrier per step

        // publish progress for steps < t (their STGs precede this barrier)
        if (tid == 0 && t > 0 && (t % 10) == 0) {
            __threadfence();
            *(volatile int*)&g_prog = t;       // steps 0..t-1 ready
        }

        // ---- combine gates; every warp redundantly updates its h registers
        if (act) {
            float2 rv = *reinterpret_cast<float2*>(&gate_sh[buf][0][c0]);
            float2 zv = *reinterpret_cast<float2*>(&gate_sh[buf][1][c0]);
            float2 lv = *reinterpret_cast<float2*>(&gate_sh[buf][2][c0]);
            float n0 = fast_tanh(rv.x * lv.x);
            float n1 = fast_tanh(rv.y * lv.y);
            h0 = zv.x * (h0 - n0) + n0;        // (1-z)*n + z*h
            h1 = zv.y * (h1 - n1) + n1;
            if (g == owner)                    // split STG issue across warps
                *reinterpret_cast<float2*>(&g_hs[t * HH + c0]) = make_float2(h0, h1);
        }
    }

    __syncthreads();                           // all warps issued final STGs
    if (tid == 0) {
        __threadfence();
        *(volatile int*)&g_prog = TT;          // all steps ready
    }
}

// ---------------------------------------------------------------------------
// nat body (CTAs 1..100): per-timestep epilogue, 96 threads.
// W_dense column + bias prefetched into registers BEFORE the spin-wait so the
// post-publish tail is minimal.
// Output layout (fp32): [Sigma T*Z*Z][mu T*Z][J T*Z*Z][h_nat T*Z]
// ---------------------------------------------------------------------------
__device__ __forceinline__ void nat_body(
    int t,
    const float* __restrict__ W_dense,
    const float* __restrict__ b_dense,
    float* __restrict__ out)
{
    const int tid = threadIdx.x;

    __shared__ float hsh[HH];
    __shared__ float osh[OUTD];
    __shared__ float L   [ZZ][ZZ];
    __shared__ float rdia[ZZ];
    __shared__ float Li  [ZZ][ZZ];
    __shared__ float Jsh [ZZ][ZZ];

    // ---- prefetch (overlaps with the recurrence; off critical path)
    float wcol[HH];
    float bv = 0.f;
    if (tid < OUTD) {
        bv = b_dense[tid];
        #pragma unroll
        for (int i = 0; i < HH; i++)
            wcol[i] = W_dense[i * OUTD + tid];
    }

    // ---- wait until the recurrence has published this timestep
    if (tid == 0) {
        while (*(volatile int*)&g_prog < t + 1) __nanosleep(64);
        __threadfence();
    }
    __syncthreads();

    if (tid < HH) hsh[tid] = g_hs[t * HH + tid];
    __syncthreads();

    // dense: out[o] = b[o] + sum_i hs[t][i] * W_dense[i][o]
    if (tid < OUTD) {
        float a = bv;
        #pragma unroll
        for (int i = 0; i < HH; i++)
            a = fmaf(hsh[i], wcol[i], a);
        osh[tid] = a;
    }
    __syncthreads();

    // build lower-triangular L from flat part; softplus on diagonal
    if (tid < NTRI) {                               // 55 < 96: single shot OK
        int k = tid;
        int r = (int)((sqrtf(8.0f * k + 1.0f) - 1.0f) * 0.5f);
        int c = k - r * (r + 1) / 2;
        float v = osh[ZZ + k];
        if (c == r) {
            v = fmaxf(v, 0.0f) + log1pf(__expf(-fabsf(v)));
            rdia[r] = __fdividef(1.0f, v);
        }
        L[r][c] = v;
    }
    __syncthreads();

    const int SIG_OFF = 0;
    const int MU_OFF  = TT * ZZ * ZZ;
    const int J_OFF   = MU_OFF + TT * ZZ;
    const int HN_OFF  = J_OFF + TT * ZZ * ZZ;

    // mu
    if (tid < ZZ) out[MU_OFF + t * ZZ + tid] = osh[tid];

    // Sigma = L L^T  (100 entries > 96 threads: stride)
    for (int idx = tid; idx < ZZ * ZZ; idx += NTHREADS) {
        int i = idx / ZZ, jj = idx % ZZ;
        int m = (i < jj) ? i : jj;
        float sacc = 0.f;
        for (int k = 0; k <= m; k++) sacc = fmaf(L[i][k], L[jj][k], sacc);
        out[SIG_OFF + t * ZZ * ZZ + idx] = sacc;
    }

    // L^{-1}: forward substitution, one column per thread (tid = column jc)
    if (tid < ZZ) {
        const int jc = tid;
        float x[ZZ];
        #pragma unroll
        for (int i = 0; i < ZZ; i++) {
            if (i < jc) { x[i] = 0.f; continue; }
            float s2 = (i == jc) ? 1.0f : 0.0f;
            #pragma unroll
            for (int k = 0; k < ZZ; k++)
                if (k >= jc && k < i) s2 -= L[i][k] * x[k];
            x[i] = s2 * rdia[i];
            Li[i][jc] = x[i];
        }
    }
    __syncthreads();

    // J = L^{-T} L^{-1} : J[i][j] = sum_{k>=max(i,j)} Li[k][i]*Li[k][j]
    for (int idx = tid; idx < ZZ * ZZ; idx += NTHREADS) {
        int i = idx / ZZ, jj = idx % ZZ;
        int m = (i > jj) ? i : jj;
        float sacc = 0.f;
        for (int k = m; k < ZZ; k++) sacc = fmaf(Li[k][i], Li[k][jj], sacc);
        Jsh[i][jj] = sacc;
        out[J_OFF + t * ZZ * ZZ + idx] = sacc;
    }
    __syncthreads();

    // h_nat = J @ mu
    if (tid < ZZ) {
        float sacc = 0.f;
        #pragma unroll
        for (int jj = 0; jj < ZZ; jj++)
            sacc = fmaf(Jsh[tid][jj], osh[jj], sacc);
        out[HN_OFF + t * ZZ + tid] = sacc;
    }
}

// ---------------------------------------------------------------------------
// Fused kernel: CTA 0 = recurrence producer; CTAs 1..100 = nat consumers.
// All 101 CTAs are co-resident (<= 148 SMs), so the spin-wait cannot deadlock.
// ---------------------------------------------------------------------------
__global__ void __launch_bounds__(NTHREADS, 1) gru_fused_kernel(
    const float* __restrict__ carry_init,
    const float* __restrict__ W_hr, const float* __restrict__ b_hr,
    const float* __restrict__ s_r,  const float* __restrict__ o_r,
    const float* __restrict__ W_hz, const float* __restrict__ b_hz,
    const float* __restrict__ s_z,  const float* __restrict__ o_z,
    const float* __restrict__ W_hn, const float* __restrict__ b_hn,
    const float* __restrict__ s_n,  const float* __restrict__ o_n,
    const float* __restrict__ W_dense,
    const float* __restrict__ b_dense,
    float* __restrict__ out)
{
    if (blockIdx.x == 0) {
        recurrence_body(carry_init,
                        W_hr, b_hr, s_r, o_r,
                        W_hz, b_hz, s_z, o_z,
                        W_hn, b_hn, s_n, o_n);
    } else {
        nat_body(blockIdx.x - 1, W_dense, b_dense, out);
    }
}

// ---------------------------------------------------------------------------
// Launch. Input order (metadata): carry_init, W_hr, b_hr, s_r, o_r,
// W_hz, b_hz, s_z, o_z, W_hn, b_hn, s_n, o_n, W_dense, b_dense
// ---------------------------------------------------------------------------
extern "C" void kernel_launch(void* const* d_in, const int* in_sizes, int n_in,
                              void* d_out, int out_size)
{
    const float* carry   = (const float*)d_in[0];
    const float* W_hr    = (const float*)d_in[1];
    const float* b_hr    = (const float*)d_in[2];
    const float* s_r     = (const float*)d_in[3];
    const float* o_r     = (const float*)d_in[4];
    const float* W_hz    = (const float*)d_in[5];
    const float* b_hz    = (const float*)d_in[6];
    const float* s_z     = (const float*)d_in[7];
    const float* o_z     = (const float*)d_in[8];
    const float* W_hn    = (const float*)d_in[9];
    const float* b_hn    = (const float*)d_in[10];
    const float* s_n     = (const float*)d_in[11];
    const float* o_n     = (const float*)d_in[12];
    const float* W_dense = (const float*)d_in[13];
    const float* b_dense = (const float*)d_in[14];

    gru_fused_kernel<<<1 + TT, NTHREADS>>>(carry,
        W_hr, b_hr, s_r, o_r,
        W_hz, b_hz, s_z, o_z,
        W_hn, b_hn, s_n, o_n,
        W_dense, b_dense, (float*)d_out);
}

// round 8
// speedup vs baseline: 1.0437x; 1.0437x over previous
#include <cuda_runtime.h>
#include <math.h>

#define TT  100
#define HH  50
#define ZZ  10
#define OUTD 65          // ZZ + ZZ*(ZZ+1)/2
#define NTRI 55          // ZZ*(ZZ+1)/2
#define LN_EPS 1e-6f
#define NTHREADS 96

// scratch for hs (T x H) + progress flag — __device__ globals, no allocation
__device__ float g_hs[TT * HH];
__device__ int   g_prog;          // count of published steps

// ---------------- packed f32x2 helpers (Blackwell) ----------------
__device__ __forceinline__ unsigned long long pk2(float lo, float hi) {
    unsigned long long r;
    asm("mov.b64 %0, {%1, %2};" : "=l"(r) : "f"(lo), "f"(hi));
    return r;
}
__device__ __forceinline__ void upk2(unsigned long long v, float& lo, float& hi) {
    asm("mov.b64 {%0, %1}, %2;" : "=f"(lo), "=f"(hi) : "l"(v));
}
__device__ __forceinline__ unsigned long long fma2(
    unsigned long long a, unsigned long long b, unsigned long long c) {
    unsigned long long d;
    asm("fma.rn.f32x2 %0, %1, %2, %3;" : "=l"(d) : "l"(a), "l"(b), "l"(c));
    return d;
}
__device__ __forceinline__ unsigned long long add2(
    unsigned long long a, unsigned long long b) {
    unsigned long long d;
    asm("add.rn.f32x2 %0, %1, %2;" : "=l"(d) : "l"(a), "l"(b));
    return d;
}

__device__ __forceinline__ float fast_sigmoid(float x) {
    float e = __expf(-x);
    return __fdividef(1.0f, 1.0f + e);
}
__device__ __forceinline__ float fast_tanh(float x) {
    float e = __expf(-2.0f * fabsf(x));
    float t = __fdividef(1.0f - e, 1.0f + e);
    return copysignf(t, x);
}

// ---------------------------------------------------------------------------
// Recurrence (CTA 0): 3 warps, warp g owns gate g; lane l owns columns
// 2l, 2l+1 (active l < 25). h lives in DOUBLE-BUFFERED shared memory and is
// broadcast-loaded as 13 ld.shared.v2.u64 per lane (2 packed f32x2 pairs per
// 16B load) -> only 10 SHFLs/warp/step remain (the LN butterfly).
// Owner lanes (9/8/8 split) keep their h-pair in registers, do the tanh and
// publish h to the other parity buffer. Two __syncthreads per step.
// ---------------------------------------------------------------------------
__device__ __forceinline__ void recurrence_body(
    const float* __restrict__ carry_init,
    const float* __restrict__ W_hr, const float* __restrict__ b_hr,
    const float* __restrict__ s_r,  const float* __restrict__ o_r,
    const float* __restrict__ W_hz, const float* __restrict__ b_hz,
    const float* __restrict__ s_z,  const float* __restrict__ o_z,
    const float* __restrict__ W_hn, const float* __restrict__ b_hn,
    const float* __restrict__ s_n,  const float* __restrict__ o_n)
{
    __shared__ __align__(16) float h_sh[2][64];   // [parity][h], 16B aligned
    __shared__ float gate_sh[3][64];              // [gate][col] padded rows

    const int tid  = threadIdx.x;
    const int g    = tid >> 5;            // warp = gate, 0..2
    const int l    = tid & 31;            // lane
    const bool act = (l < 25);
    const int c0   = act ? 2 * l : 0;     // clamped for inactive lanes
    // owner split: warp0 lanes 0-8, warp1 lanes 9-16, warp2 lanes 17-24
    const bool own = act && ((g == 0) ? (l < 9) : (g == 1) ? (l >= 9 && l < 17)
                                                           : (l >= 17));

    const float* Wg = (g == 0) ? W_hr : (g == 1) ? W_hz : W_hn;
    const float* bg = (g == 0) ? b_hr : (g == 1) ? b_hz : b_hn;
    const float* sg = (g == 0) ? s_r  : (g == 1) ? s_z  : s_n;
    const float* og = (g == 0) ? o_r  : (g == 1) ? o_z  : o_n;

    // Weights packed along i: wx[p] = (W[2p][c0], W[2p+1][c0]); wy for c0+1.
    unsigned long long wx[25], wy[25];
    #pragma unroll
    for (int p = 0; p < 25; p++) {
        const float* r0 = Wg + (2 * p)     * HH + c0;
        const float* r1 = Wg + (2 * p + 1) * HH + c0;
        wx[p] = pk2(r0[0], r1[0]);
        wy[p] = pk2(r0[1], r1[1]);
    }
    const float b0 = bg[c0], b1 = bg[c0 + 1];
    const float sc0 = sg[c0], sc1 = sg[c0 + 1];
    const float of0 = og[c0], of1 = og[c0 + 1];

    // owner lanes keep their h pair in registers across steps
    float h0 = carry_init[c0];
    float h1 = carry_init[c0 + 1];

    if (tid < HH) h_sh[0][tid] = carry_init[tid];
    __syncthreads();

    const unsigned hs_base0 =
        (unsigned)__cvta_generic_to_shared(&h_sh[0][0]);
    const unsigned hs_stride = 64 * 4;    // bytes between parity buffers

    for (int t = 0; t < TT; t++) {
        const int buf = t & 1;

        // ---- matvec: 13 broadcast shared loads (2 packed pairs / 16B load)
        unsigned hb = hs_base0 + (unsigned)buf * hs_stride;
        unsigned long long hp[26];
        #pragma unroll
        for (int q = 0; q < 12; q++) {
            asm("ld.shared.v2.u64 {%0, %1}, [%2];"
                : "=l"(hp[2 * q]), "=l"(hp[2 * q + 1])
                : "r"(hb + 16u * q));
        }
        asm("ld.shared.u64 %0, [%1];" : "=l"(hp[24]) : "r"(hb + 192u));

        unsigned long long axe = 0ull, axo = 0ull, aye = 0ull, ayo = 0ull;
        #pragma unroll
        for (int p = 0; p < 25; p++) {
            if (p & 1) { axo = fma2(hp[p], wx[p], axo); ayo = fma2(hp[p], wy[p], ayo); }
            else       { axe = fma2(hp[p], wx[p], axe); aye = fma2(hp[p], wy[p], aye); }
        }
        float e0, e1, f0, f1;
        upk2(add2(axe, axo), e0, e1);
        upk2(add2(aye, ayo), f0, f1);
        float px = e0 + e1 + b0;
        float py = f0 + f1 + b1;

        // ---- in-warp layernorm stats: 5-step butterfly (only SHFLs left)
        float sv = 0.f, qv = 0.f;
        if (act) { sv = px + py; qv = px * px + py * py; }
        #pragma unroll
        for (int off = 16; off; off >>= 1) {
            sv += __shfl_xor_sync(0xffffffffu, sv, off);
            qv += __shfl_xor_sync(0xffffffffu, qv, off);
        }
        float mean = sv * (1.0f / HH);
        float var  = qv * (1.0f / HH) - mean * mean;
        float inv  = rsqrtf(var + LN_EPS);

        float nx = (px - mean) * inv * sc0 + of0;
        float ny = (py - mean) * inv * sc1 + of1;

        float gx, gy;
        if (g < 2) { gx = fast_sigmoid(nx); gy = fast_sigmoid(ny); }
        else       { gx = nx;               gy = ny;               }

        if (act)
            *reinterpret_cast<float2*>(&gate_sh[g][c0]) = make_float2(gx, gy);
        __syncthreads();                       // BAR1: gates ready

        // ---- owner lanes combine gates + publish h to other parity buffer
        if (own) {
            float2 rv = *reinterpret_cast<float2*>(&gate_sh[0][c0]);
            float2 zv = *reinterpret_cast<float2*>(&gate_sh[1][c0]);
            float2 lv = *reinterpret_cast<float2*>(&gate_sh[2][c0]);
            float n0 = fast_tanh(rv.x * lv.x);
            float n1 = fast_tanh(rv.y * lv.y);
            h0 = zv.x * (h0 - n0) + n0;        // (1-z)*n + z*h
            h1 = zv.y * (h1 - n1) + n1;
            *reinterpret_cast<float2*>(&h_sh[buf ^ 1][c0]) = make_float2(h0, h1);
            *reinterpret_cast<float2*>(&g_hs[t * HH + c0]) = make_float2(h0, h1);
        }
        // publish steps 0..t to consumer CTAs every 10 steps
        if ((t % 10) == 9) __threadfence();
        __syncthreads();                       // BAR2: h ready
        if ((t % 10) == 9 && tid == 0)
            *(volatile int*)&g_prog = t + 1;
    }

    if (tid == 0) {
        __threadfence();
        *(volatile int*)&g_prog = TT;          // safety net
    }
}

// ---------------------------------------------------------------------------
// nat body (CTAs 1..100): per-timestep epilogue, 96 threads.
// W_dense column + bias prefetched BEFORE the spin-wait.
// Output layout (fp32): [Sigma T*Z*Z][mu T*Z][J T*Z*Z][h_nat T*Z]
// ---------------------------------------------------------------------------
__device__ __forceinline__ void nat_body(
    int t,
    const float* __restrict__ W_dense,
    const float* __restrict__ b_dense,
    float* __restrict__ out)
{
    const int tid = threadIdx.x;

    __shared__ float hsh[HH];
    __shared__ float osh[OUTD];
    __shared__ float L   [ZZ][ZZ];
    __shared__ float rdia[ZZ];
    __shared__ float Li  [ZZ][ZZ];
    __shared__ float Jsh [ZZ][ZZ];

    // ---- prefetch (overlaps with the recurrence; off critical path)
    float wcol[HH];
    float bv = 0.f;
    if (tid < OUTD) {
        bv = b_dense[tid];
        #pragma unroll
        for (int i = 0; i < HH; i++)
            wcol[i] = W_dense[i * OUTD + tid];
    }

    // ---- wait until the recurrence has published this timestep
    if (tid == 0) {
        while (*(volatile int*)&g_prog < t + 1) __nanosleep(64);
        __threadfence();
    }
    __syncthreads();

    if (tid < HH) hsh[tid] = g_hs[t * HH + tid];
    __syncthreads();

    // dense: out[o] = b[o] + sum_i hs[t][i] * W_dense[i][o]
    if (tid < OUTD) {
        float a = bv;
        #pragma unroll
        for (int i = 0; i < HH; i++)
            a = fmaf(hsh[i], wcol[i], a);
        osh[tid] = a;
    }
    __syncthreads();

    // build lower-triangular L from flat part; softplus on diagonal
    if (tid < NTRI) {                               // 55 < 96: single shot OK
        int k = tid;
        int r = (int)((sqrtf(8.0f * k + 1.0f) - 1.0f) * 0.5f);
        int c = k - r * (r + 1) / 2;
        float v = osh[ZZ + k];
        if (c == r) {
            v = fmaxf(v, 0.0f) + log1pf(__expf(-fabsf(v)));
            rdia[r] = __fdividef(1.0f, v);
        }
        L[r][c] = v;
    }
    __syncthreads();

    const int SIG_OFF = 0;
    const int MU_OFF  = TT * ZZ * ZZ;
    const int J_OFF   = MU_OFF + TT * ZZ;
    const int HN_OFF  = J_OFF + TT * ZZ * ZZ;

    // mu
    if (tid < ZZ) out[MU_OFF + t * ZZ + tid] = osh[tid];

    // Sigma = L L^T  (100 entries > 96 threads: stride)
    for (int idx = tid; idx < ZZ * ZZ; idx += NTHREADS) {
        int i = idx / ZZ, jj = idx % ZZ;
        int m = (i < jj) ? i : jj;
        float sacc = 0.f;
        for (int k = 0; k <= m; k++) sacc = fmaf(L[i][k], L[jj][k], sacc);
        out[SIG_OFF + t * ZZ * ZZ + idx] = sacc;
    }

    // L^{-1}: forward substitution, one column per thread (tid = column jc)
    if (tid < ZZ) {
        const int jc = tid;
        float x[ZZ];
        #pragma unroll
        for (int i = 0; i < ZZ; i++) {
            if (i < jc) { x[i] = 0.f; continue; }
            float s2 = (i == jc) ? 1.0f : 0.0f;
            #pragma unroll
            for (int k = 0; k < ZZ; k++)
                if (k >= jc && k < i) s2 -= L[i][k] * x[k];
            x[i] = s2 * rdia[i];
            Li[i][jc] = x[i];
        }
    }
    __syncthreads();

    // J = L^{-T} L^{-1} : J[i][j] = sum_{k>=max(i,j)} Li[k][i]*Li[k][j]
    for (int idx = tid; idx < ZZ * ZZ; idx += NTHREADS) {
        int i = idx / ZZ, jj = idx % ZZ;
        int m = (i > jj) ? i : jj;
        float sacc = 0.f;
        for (int k = m; k < ZZ; k++) sacc = fmaf(Li[k][i], Li[k][jj], sacc);
        Jsh[i][jj] = sacc;
        out[J_OFF + t * ZZ * ZZ + idx] = sacc;
    }
    __syncthreads();

    // h_nat = J @ mu
    if (tid < ZZ) {
        float sacc = 0.f;
        #pragma unroll
        for (int jj = 0; jj < ZZ; jj++)
            sacc = fmaf(Jsh[tid][jj], osh[jj], sacc);
        out[HN_OFF + t * ZZ + tid] = sacc;
    }
}

// ---------------------------------------------------------------------------
// Fused kernel: CTA 0 = recurrence producer; CTAs 1..100 = nat consumers.
// All 101 CTAs are co-resident (<= 148 SMs), so the spin-wait cannot deadlock.
// ---------------------------------------------------------------------------
__global__ void __launch_bounds__(NTHREADS, 1) gru_fused_kernel(
    const float* __restrict__ carry_init,
    const float* __restrict__ W_hr, const float* __restrict__ b_hr,
    const float* __restrict__ s_r,  const float* __restrict__ o_r,
    const float* __restrict__ W_hz, const float* __restrict__ b_hz,
    const float* __restrict__ s_z,  const float* __restrict__ o_z,
    const float* __restrict__ W_hn, const float* __restrict__ b_hn,
    const float* __restrict__ s_n,  const float* __restrict__ o_n,
    const float* __restrict__ W_dense,
    const float* __restrict__ b_dense,
    float* __restrict__ out)
{
    if (blockIdx.x == 0) {
        recurrence_body(carry_init,
                        W_hr, b_hr, s_r, o_r,
                        W_hz, b_hz, s_z, o_z,
                        W_hn, b_hn, s_n, o_n);
    } else {
        nat_body(blockIdx.x - 1, W_dense, b_dense, out);
    }
}

// ---------------------------------------------------------------------------
// Launch. Input order (metadata): carry_init, W_hr, b_hr, s_r, o_r,
// W_hz, b_hz, s_z, o_z, W_hn, b_hn, s_n, o_n, W_dense, b_dense
// ---------------------------------------------------------------------------
extern "C" void kernel_launch(void* const* d_in, const int* in_sizes, int n_in,
                              void* d_out, int out_size)
{
    const float* carry   = (const float*)d_in[0];
    const float* W_hr    = (const float*)d_in[1];
    const float* b_hr    = (const float*)d_in[2];
    const float* s_r     = (const float*)d_in[3];
    const float* o_r     = (const float*)d_in[4];
    const float* W_hz    = (const float*)d_in[5];
    const float* b_hz    = (const float*)d_in[6];
    const float* s_z     = (const float*)d_in[7];
    const float* o_z     = (const float*)d_in[8];
    const float* W_hn    = (const float*)d_in[9];
    const float* b_hn    = (const float*)d_in[10];
    const float* s_n     = (const float*)d_in[11];
    const float* o_n     = (const float*)d_in[12];
    const float* W_dense = (const float*)d_in[13];
    const float* b_dense = (const float*)d_in[14];

    gru_fused_kernel<<<1 + TT, NTHREADS>>>(carry,
        W_hr, b_hr, s_r, o_r,
        W_hz, b_hz, s_z, o_z,
        W_hn, b_hn, s_n, o_n,
        W_dense, b_dense, (float*)d_out);
}